// round 1
// baseline (speedup 1.0000x reference)
#include <cuda_runtime.h>
#include <cuda_bf16.h>
#include <math.h>

// Problem shapes (fixed by the dataset)
#define B_  4096
#define L_  200
#define D_  256
#define BN_EPS 1e-5f

// -------- scratch (no allocations allowed) --------
__device__ float g_pooled[B_ * D_];     // 4 MB
__device__ float g_z[B_ * D_];          // 4 MB
__device__ float g_part[2 * 32 * D_];   // column partial sums / sumsq
__device__ float g_mu[D_];
__device__ float g_rstd[D_];
__device__ float g_lossp[256];

// ============================================================
// Kernel 1: ragged gather + mean pool.  1 block = 1 batch row.
// 256 threads, thread d accumulates dim d. Tokens staged in smem.
// Unroll 8 over L for MLP.
// ============================================================
__global__ void __launch_bounds__(256) pool_kernel(
    const int* __restrict__ tokens,
    const int* __restrict__ lengths,
    const float* __restrict__ emb)
{
    const int b   = blockIdx.x;
    const int tid = threadIdx.x;
    __shared__ int s_tok[L_];

    const int len = lengths[b];
    // stage token row
    if (tid < L_) s_tok[tid] = tokens[b * L_ + tid];
    __syncthreads();

    float acc0 = 0.f, acc1 = 0.f;
    int l = 0;
    // 8-way unrolled: 8 independent LDGs in flight per thread
    for (; l + 8 <= len; l += 8) {
        const float* r0 = emb + (size_t)s_tok[l + 0] * D_;
        const float* r1 = emb + (size_t)s_tok[l + 1] * D_;
        const float* r2 = emb + (size_t)s_tok[l + 2] * D_;
        const float* r3 = emb + (size_t)s_tok[l + 3] * D_;
        const float* r4 = emb + (size_t)s_tok[l + 4] * D_;
        const float* r5 = emb + (size_t)s_tok[l + 5] * D_;
        const float* r6 = emb + (size_t)s_tok[l + 6] * D_;
        const float* r7 = emb + (size_t)s_tok[l + 7] * D_;
        float v0 = __ldg(r0 + tid); float v1 = __ldg(r1 + tid);
        float v2 = __ldg(r2 + tid); float v3 = __ldg(r3 + tid);
        float v4 = __ldg(r4 + tid); float v5 = __ldg(r5 + tid);
        float v6 = __ldg(r6 + tid); float v7 = __ldg(r7 + tid);
        acc0 += (v0 + v1) + (v2 + v3);
        acc1 += (v4 + v5) + (v6 + v7);
    }
    for (; l < len; ++l)
        acc0 += __ldg(emb + (size_t)s_tok[l] * D_ + tid);

    g_pooled[(size_t)b * D_ + tid] = (acc0 + acc1) / (float)len;
}

// ============================================================
// Kernel 2: Z = pooled @ W1^T + b1.  [4096,256]x[256,256]
// Tiled fp32 GEMM: BM=BN=BK=64, 256 threads, 4x4 thread tiles.
// Both A and W are K-contiguous row-major (C = A * W^T form).
// ============================================================
#define GBM 64
#define GBN 64
#define GBK 64
__global__ void __launch_bounds__(256) gemm_kernel(
    const float* __restrict__ A,    // g_pooled [B, D]
    const float* __restrict__ W,    // W1 [D, D] (row j = output col j)
    const float* __restrict__ b1,
    float* __restrict__ Z)
{
    __shared__ float As[GBK][GBM + 4];  // [k][m]
    __shared__ float Bs[GBK][GBN + 4];  // [k][n]

    const int tid = threadIdx.x;
    const int bm = blockIdx.y * GBM;
    const int bn = blockIdx.x * GBN;
    const int tx = tid & 15;      // 0..15 -> cols (x4)
    const int ty = tid >> 4;      // 0..15 -> rows (x4)

    float c[4][4] = {};

    for (int k0 = 0; k0 < D_; k0 += GBK) {
        // cooperative load: 64x64 A-tile and 64x64 W-tile, transposed into smem
        #pragma unroll
        for (int j = 0; j < 4; ++j) {
            int idx = tid + j * 256;       // float4 slot 0..1023
            int m   = idx >> 4;            // 0..63
            int k4  = idx & 15;            // 0..15
            float4 va = *(const float4*)&A[(size_t)(bm + m) * D_ + k0 + k4 * 4];
            As[k4 * 4 + 0][m] = va.x; As[k4 * 4 + 1][m] = va.y;
            As[k4 * 4 + 2][m] = va.z; As[k4 * 4 + 3][m] = va.w;
            float4 vb = *(const float4*)&W[(size_t)(bn + m) * D_ + k0 + k4 * 4];
            Bs[k4 * 4 + 0][m] = vb.x; Bs[k4 * 4 + 1][m] = vb.y;
            Bs[k4 * 4 + 2][m] = vb.z; Bs[k4 * 4 + 3][m] = vb.w;
        }
        __syncthreads();

        #pragma unroll
        for (int kk = 0; kk < GBK; ++kk) {
            float4 a = *(const float4*)&As[kk][ty * 4];
            float4 bv = *(const float4*)&Bs[kk][tx * 4];
            float ar[4] = {a.x, a.y, a.z, a.w};
            float br[4] = {bv.x, bv.y, bv.z, bv.w};
            #pragma unroll
            for (int i = 0; i < 4; ++i)
                #pragma unroll
                for (int jj = 0; jj < 4; ++jj)
                    c[i][jj] = fmaf(ar[i], br[jj], c[i][jj]);
        }
        __syncthreads();
    }

    #pragma unroll
    for (int i = 0; i < 4; ++i) {
        int row = bm + ty * 4 + i;
        #pragma unroll
        for (int jj = 0; jj < 4; ++jj) {
            int col = bn + tx * 4 + jj;
            Z[(size_t)row * D_ + col] = c[i][jj] + b1[col];
        }
    }
}

// ============================================================
// Kernel 3: per-chunk column sums/sumsq (deterministic, no atomics)
// grid 32 blocks x 256 threads; block i handles rows [i*128, i*128+128)
// ============================================================
__global__ void __launch_bounds__(256) stats_part_kernel(const float* __restrict__ Z)
{
    const int d   = threadIdx.x;
    const int blk = blockIdx.x;
    float s = 0.f, ss = 0.f;
    const int r0 = blk * 128;
    #pragma unroll 4
    for (int r = r0; r < r0 + 128; ++r) {
        float v = Z[(size_t)r * D_ + d];
        s  += v;
        ss = fmaf(v, v, ss);
    }
    g_part[blk * D_ + d]            = s;
    g_part[32 * D_ + blk * D_ + d]  = ss;
}

// Kernel 4: finalize mu / rstd.  1 block, 256 threads.
__global__ void __launch_bounds__(256) stats_final_kernel()
{
    const int d = threadIdx.x;
    float s = 0.f, ss = 0.f;
    #pragma unroll
    for (int i = 0; i < 32; ++i) {
        s  += g_part[i * D_ + d];
        ss += g_part[32 * D_ + i * D_ + d];
    }
    float mu  = s * (1.f / (float)B_);
    float var = ss * (1.f / (float)B_) - mu * mu;
    g_mu[d]   = mu;
    g_rstd[d] = rsqrtf(var + BN_EPS);
}

// ============================================================
// Kernel 5: BN + ReLU + dot(w2) + BCE partial loss.
// grid 256 blocks x 256 threads, 16 rows per block.
// logits -> out[1 + b]; per-block loss partial -> g_lossp.
// ============================================================
__global__ void __launch_bounds__(256) head_kernel(
    const float* __restrict__ Z,
    const float* __restrict__ gamma,
    const float* __restrict__ beta,
    const float* __restrict__ w2,
    const float* __restrict__ b2,
    const float* __restrict__ t,
    float* __restrict__ out)
{
    const int tid  = threadIdx.x;
    const int lane = tid & 31;
    const int warp = tid >> 5;

    const float g  = gamma[tid] * g_rstd[tid];
    const float be = beta[tid] - g * g_mu[tid];
    const float w  = w2[tid];
    const float b2v = b2[0];

    __shared__ float red[8];
    float lossacc = 0.f;

    for (int r = 0; r < 16; ++r) {
        const int b = blockIdx.x * 16 + r;
        float z = Z[(size_t)b * D_ + tid];
        float h = fmaxf(fmaf(g, z, be), 0.f);
        float p = h * w;
        #pragma unroll
        for (int off = 16; off > 0; off >>= 1)
            p += __shfl_xor_sync(0xFFFFFFFFu, p, off);
        if (lane == 0) red[warp] = p;
        __syncthreads();
        if (tid == 0) {
            float l = b2v;
            #pragma unroll
            for (int wi = 0; wi < 8; ++wi) l += red[wi];
            out[1 + b] = l;
            float tb = t[b];
            lossacc += fmaxf(l, 0.f) - l * tb + log1pf(expf(-fabsf(l)));
        }
        __syncthreads();  // protect red[] reuse
    }
    if (tid == 0) g_lossp[blockIdx.x] = lossacc;
}

// Kernel 6: final loss reduction.  1 block, 256 threads.
__global__ void __launch_bounds__(256) loss_final_kernel(float* __restrict__ out)
{
    const int tid  = threadIdx.x;
    const int lane = tid & 31;
    const int warp = tid >> 5;
    __shared__ float red[8];
    float v = g_lossp[tid];
    #pragma unroll
    for (int off = 16; off > 0; off >>= 1)
        v += __shfl_xor_sync(0xFFFFFFFFu, v, off);
    if (lane == 0) red[warp] = v;
    __syncthreads();
    if (tid == 0) {
        float s = 0.f;
        #pragma unroll
        for (int wi = 0; wi < 8; ++wi) s += red[wi];
        out[0] = s * (1.f / (float)B_);
    }
}

// ============================================================
// launch
// ============================================================
extern "C" void kernel_launch(void* const* d_in, const int* in_sizes, int n_in,
                              void* d_out, int out_size)
{
    const int*   tokens  = (const int*)d_in[0];
    const int*   lengths = (const int*)d_in[1];
    const float* t       = (const float*)d_in[2];
    const float* emb     = (const float*)d_in[3];
    const float* W1      = (const float*)d_in[4];
    const float* b1      = (const float*)d_in[5];
    const float* gamma   = (const float*)d_in[6];
    const float* beta    = (const float*)d_in[7];
    const float* w2      = (const float*)d_in[8];
    const float* b2      = (const float*)d_in[9];
    float* out = (float*)d_out;

    float* pooled; cudaGetSymbolAddress((void**)&pooled, g_pooled);
    float* z;      cudaGetSymbolAddress((void**)&z,      g_z);

    pool_kernel<<<B_, 256>>>(tokens, lengths, emb);

    dim3 ggrid(D_ / GBN, B_ / GBM);   // (4, 64)
    gemm_kernel<<<ggrid, 256>>>(pooled, W1, b1, z);

    stats_part_kernel<<<32, 256>>>(z);
    stats_final_kernel<<<1, 256>>>();

    head_kernel<<<B_ / 16, 256>>>(z, gamma, beta, w2, b2, t, out);
    loss_final_kernel<<<1, 256>>>(out);
}

// round 2
// speedup vs baseline: 1.0496x; 1.0496x over previous
#include <cuda_runtime.h>
#include <cuda_bf16.h>
#include <math.h>

// Problem shapes (fixed by the dataset)
#define B_  4096
#define L_  200
#define D_  256
#define BN_EPS 1e-5f

// -------- scratch (no allocations allowed) --------
__device__ float g_pooled[B_ * D_];          // 4 MB
__device__ float g_z[B_ * D_];               // 4 MB
__device__ float g_part[2 * 64 * D_];        // per-row-block col sums / sumsq
__device__ float g_lossp[B_ / 32];           // 128 loss partials

// f32x2 packed FMA helpers
#define FMA2(acc, a, b) \
    asm("fma.rn.f32x2 %0, %1, %2, %0;" : "+l"(acc) : "l"(a), "l"(b))
#define UNPACK2(lo, hi, in) \
    asm("mov.b64 {%0, %1}, %2;" : "=f"(lo), "=f"(hi) : "l"(in))

// ============================================================
// Kernel 1: ragged gather + mean pool.  1 block = 1 batch row.
// 256 threads, thread d accumulates dim d. Tokens staged in smem.
// ============================================================
__global__ void __launch_bounds__(256) pool_kernel(
    const int* __restrict__ tokens,
    const int* __restrict__ lengths,
    const float* __restrict__ emb)
{
    const int b   = blockIdx.x;
    const int tid = threadIdx.x;
    __shared__ int s_tok[L_];

    const int len = lengths[b];
    if (tid < L_) s_tok[tid] = tokens[b * L_ + tid];
    __syncthreads();

    float acc0 = 0.f, acc1 = 0.f;
    int l = 0;
    for (; l + 8 <= len; l += 8) {
        const float* r0 = emb + (size_t)s_tok[l + 0] * D_;
        const float* r1 = emb + (size_t)s_tok[l + 1] * D_;
        const float* r2 = emb + (size_t)s_tok[l + 2] * D_;
        const float* r3 = emb + (size_t)s_tok[l + 3] * D_;
        const float* r4 = emb + (size_t)s_tok[l + 4] * D_;
        const float* r5 = emb + (size_t)s_tok[l + 5] * D_;
        const float* r6 = emb + (size_t)s_tok[l + 6] * D_;
        const float* r7 = emb + (size_t)s_tok[l + 7] * D_;
        float v0 = __ldg(r0 + tid); float v1 = __ldg(r1 + tid);
        float v2 = __ldg(r2 + tid); float v3 = __ldg(r3 + tid);
        float v4 = __ldg(r4 + tid); float v5 = __ldg(r5 + tid);
        float v6 = __ldg(r6 + tid); float v7 = __ldg(r7 + tid);
        acc0 += (v0 + v1) + (v2 + v3);
        acc1 += (v4 + v5) + (v6 + v7);
    }
    for (; l < len; ++l)
        acc0 += __ldg(emb + (size_t)s_tok[l] * D_ + tid);

    g_pooled[(size_t)b * D_ + tid] = (acc0 + acc1) / (float)len;
}

// ============================================================
// Kernel 2: Z = pooled @ W1^T + b1  (f32x2 packed FMA) with fused
// per-row-block column sum/sumsq stats in the epilogue.
// BM=BN=BK=64, 256 threads, 4x4 thread tiles.
// Trick: keep a pair-swapped copy of the B tile (Bsw) so every
// fma.rn.f32x2 operand is a natural register pair — no dup MOVs.
// ============================================================
#define GBM 64
#define GBN 64
#define GBK 64
__global__ void __launch_bounds__(256) gemm_kernel(
    const float* __restrict__ A,    // g_pooled [B, D]
    const float* __restrict__ W,    // W1 [D, D] (row j = output col j)
    const float* __restrict__ b1,
    float* __restrict__ Z)
{
    __shared__ __align__(16) float As [GBK][GBM + 4];  // [k][m]
    __shared__ __align__(16) float Bs [GBK][GBN + 4];  // [k][n]
    __shared__ __align__(16) float Bsw[GBK][GBN + 4];  // [k][n^1] pair-swapped

    const int tid = threadIdx.x;
    const int bm = blockIdx.y * GBM;
    const int bn = blockIdx.x * GBN;
    const int tx = tid & 15;      // 0..15 -> col quad
    const int ty = tid >> 4;      // 0..15 -> row quad

    // accumulators: d = diagonal pairs, x = anti-diagonal pairs
    unsigned long long d00 = 0, d01 = 0, d10 = 0, d11 = 0;
    unsigned long long x00 = 0, x01 = 0, x10 = 0, x11 = 0;

    for (int k0 = 0; k0 < D_; k0 += GBK) {
        #pragma unroll
        for (int j = 0; j < 4; ++j) {
            int idx = tid + j * 256;
            int m   = idx >> 4;            // 0..63
            int k4  = idx & 15;            // 0..15
            float4 va = *(const float4*)&A[(size_t)(bm + m) * D_ + k0 + k4 * 4];
            As[k4 * 4 + 0][m] = va.x; As[k4 * 4 + 1][m] = va.y;
            As[k4 * 4 + 2][m] = va.z; As[k4 * 4 + 3][m] = va.w;
            float4 vb = *(const float4*)&W[(size_t)(bn + m) * D_ + k0 + k4 * 4];
            Bs[k4 * 4 + 0][m] = vb.x; Bs[k4 * 4 + 1][m] = vb.y;
            Bs[k4 * 4 + 2][m] = vb.z; Bs[k4 * 4 + 3][m] = vb.w;
            int ms = m ^ 1;                // swapped n within pairs
            Bsw[k4 * 4 + 0][ms] = vb.x; Bsw[k4 * 4 + 1][ms] = vb.y;
            Bsw[k4 * 4 + 2][ms] = vb.z; Bsw[k4 * 4 + 3][ms] = vb.w;
        }
        __syncthreads();

        #pragma unroll
        for (int kk = 0; kk < GBK; ++kk) {
            ulonglong2 av = *(const ulonglong2*)&As [kk][ty * 4];
            ulonglong2 bv = *(const ulonglong2*)&Bs [kk][tx * 4];
            ulonglong2 bw = *(const ulonglong2*)&Bsw[kk][tx * 4];
            FMA2(d00, av.x, bv.x);   // {a0b0, a1b1}
            FMA2(x00, av.x, bw.x);   // {a0b1, a1b0}
            FMA2(d01, av.x, bv.y);   // {a0b2, a1b3}
            FMA2(x01, av.x, bw.y);   // {a0b3, a1b2}
            FMA2(d10, av.y, bv.x);   // {a2b0, a3b1}
            FMA2(x10, av.y, bw.x);   // {a2b1, a3b0}
            FMA2(d11, av.y, bv.y);   // {a2b2, a3b3}
            FMA2(x11, av.y, bw.y);   // {a2b3, a3b2}
        }
        __syncthreads();
    }

    // unpack accumulators into cc[row][col]
    float cc[4][4];
    UNPACK2(cc[0][0], cc[1][1], d00); UNPACK2(cc[0][1], cc[1][0], x00);
    UNPACK2(cc[0][2], cc[1][3], d01); UNPACK2(cc[0][3], cc[1][2], x01);
    UNPACK2(cc[2][0], cc[3][1], d10); UNPACK2(cc[2][1], cc[3][0], x10);
    UNPACK2(cc[2][2], cc[3][3], d11); UNPACK2(cc[2][3], cc[3][2], x11);

    // add bias, write Z, collect per-thread column sums/sumsq
    float s[4] = {0, 0, 0, 0}, ss[4] = {0, 0, 0, 0};
    #pragma unroll
    for (int jj = 0; jj < 4; ++jj) {
        float bias = b1[bn + tx * 4 + jj];
        #pragma unroll
        for (int i = 0; i < 4; ++i) {
            float z = cc[i][jj] + bias;
            Z[(size_t)(bm + ty * 4 + i) * D_ + bn + tx * 4 + jj] = z;
            s[jj]  += z;
            ss[jj] = fmaf(z, z, ss[jj]);
        }
    }

    // block reduction over ty (16) — reuse As storage (all threads passed
    // the final __syncthreads of the k-loop; As no longer read)
    float* rs  = &As[0][0];         // [16][64] sums
    float* rss = rs + 16 * 64;      // [16][64] sumsq
    #pragma unroll
    for (int jj = 0; jj < 4; ++jj) {
        rs [ty * 64 + tx * 4 + jj] = s[jj];
        rss[ty * 64 + tx * 4 + jj] = ss[jj];
    }
    __syncthreads();
    #pragma unroll
    for (int st = 8; st >= 1; st >>= 1) {
        if (ty < st) {
            #pragma unroll
            for (int jj = 0; jj < 4; ++jj) {
                int c = tx * 4 + jj;
                rs [ty * 64 + c] += rs [(ty + st) * 64 + c];
                rss[ty * 64 + c] += rss[(ty + st) * 64 + c];
            }
        }
        __syncthreads();
    }
    if (ty == 0) {
        #pragma unroll
        for (int jj = 0; jj < 4; ++jj) {
            int c = tx * 4 + jj;
            g_part[blockIdx.y * D_ + bn + c]            = rs [c];
            g_part[64 * D_ + blockIdx.y * D_ + bn + c]  = rss[c];
        }
    }
}

// ============================================================
// Kernel 3: fused BN-finalize + BN + ReLU + dot(w2) + BCE partials.
// grid 128 blocks x 256 threads; block handles 32 rows; warp = 4 rows.
// Phase 1: each block folds the 64 stat partials into mu/rstd (smem).
// ============================================================
__global__ void __launch_bounds__(256) head_kernel(
    const float* __restrict__ Z,
    const float* __restrict__ gamma,
    const float* __restrict__ beta,
    const float* __restrict__ w2,
    const float* __restrict__ b2,
    const float* __restrict__ t,
    float* __restrict__ out)
{
    const int tid  = threadIdx.x;
    const int lane = tid & 31;
    const int warp = tid >> 5;

    __shared__ float s_g[D_], s_be[D_], s_w[D_];
    __shared__ float red[8];

    // Phase 1: finalize BN stats for dim d = tid
    {
        float sm = 0.f, sq = 0.f;
        #pragma unroll 8
        for (int rb = 0; rb < 64; ++rb) {
            sm += g_part[rb * D_ + tid];
            sq += g_part[64 * D_ + rb * D_ + tid];
        }
        float mu   = sm * (1.f / (float)B_);
        float var  = sq * (1.f / (float)B_) - mu * mu;
        float rstd = rsqrtf(var + BN_EPS);
        float g    = gamma[tid] * rstd;
        s_g[tid]  = g;
        s_be[tid] = beta[tid] - g * mu;
        s_w[tid]  = w2[tid];
    }
    __syncthreads();

    // Phase 2: each warp processes 4 rows with 4 independent reduce chains
    const int row0 = blockIdx.x * 32 + warp * 4;
    const float b2v = b2[0];

    float acc[4] = {0.f, 0.f, 0.f, 0.f};
    #pragma unroll
    for (int k = 0; k < 8; ++k) {
        int dm = lane + 32 * k;
        float gk = s_g[dm], bek = s_be[dm], wk = s_w[dm];
        #pragma unroll
        for (int r = 0; r < 4; ++r) {
            float zv = Z[(size_t)(row0 + r) * D_ + dm];
            acc[r] += fmaxf(fmaf(gk, zv, bek), 0.f) * wk;
        }
    }
    #pragma unroll
    for (int off = 16; off > 0; off >>= 1) {
        #pragma unroll
        for (int r = 0; r < 4; ++r)
            acc[r] += __shfl_xor_sync(0xFFFFFFFFu, acc[r], off);
    }

    float lossacc = 0.f;
    if (lane == 0) {
        #pragma unroll
        for (int r = 0; r < 4; ++r) {
            float l = acc[r] + b2v;
            out[1 + row0 + r] = l;
            float tb = t[row0 + r];
            lossacc += fmaxf(l, 0.f) - l * tb + log1pf(expf(-fabsf(l)));
        }
        red[warp] = lossacc;
    }
    __syncthreads();
    if (tid == 0) {
        float sum = 0.f;
        #pragma unroll
        for (int w = 0; w < 8; ++w) sum += red[w];
        g_lossp[blockIdx.x] = sum;
    }
}

// Kernel 4: final loss reduction.  1 block, 128 threads.
__global__ void __launch_bounds__(128) loss_final_kernel(float* __restrict__ out)
{
    const int tid  = threadIdx.x;
    const int lane = tid & 31;
    const int warp = tid >> 5;
    __shared__ float red[4];
    float v = g_lossp[tid];
    #pragma unroll
    for (int off = 16; off > 0; off >>= 1)
        v += __shfl_xor_sync(0xFFFFFFFFu, v, off);
    if (lane == 0) red[warp] = v;
    __syncthreads();
    if (tid == 0)
        out[0] = (red[0] + red[1] + red[2] + red[3]) * (1.f / (float)B_);
}

// ============================================================
// launch
// ============================================================
extern "C" void kernel_launch(void* const* d_in, const int* in_sizes, int n_in,
                              void* d_out, int out_size)
{
    const int*   tokens  = (const int*)d_in[0];
    const int*   lengths = (const int*)d_in[1];
    const float* t       = (const float*)d_in[2];
    const float* emb     = (const float*)d_in[3];
    const float* W1      = (const float*)d_in[4];
    const float* b1      = (const float*)d_in[5];
    const float* gamma   = (const float*)d_in[6];
    const float* beta    = (const float*)d_in[7];
    const float* w2      = (const float*)d_in[8];
    const float* b2      = (const float*)d_in[9];
    float* out = (float*)d_out;

    float* pooled; cudaGetSymbolAddress((void**)&pooled, g_pooled);
    float* z;      cudaGetSymbolAddress((void**)&z,      g_z);

    pool_kernel<<<B_, 256>>>(tokens, lengths, emb);

    dim3 ggrid(D_ / GBN, B_ / GBM);   // (4, 64)
    gemm_kernel<<<ggrid, 256>>>(pooled, W1, b1, z);

    head_kernel<<<B_ / 32, 256>>>(z, gamma, beta, w2, b2, t, out);
    loss_final_kernel<<<1, 128>>>(out);
}